// round 9
// baseline (speedup 1.0000x reference)
#include <cuda_runtime.h>
#include <cstdint>

typedef unsigned long long ull;

#define NB 16
#define NOVER 7168
#define NP 1024
#define NIMP 768
#define NCOV 256
#define REND_ELEMS (NB*7*NP)   /* 114688 */
#define NCH 135
#define FPITCH 136
#define NSLOT 68               /* channel pairs per point: slot s -> c=2s,2s+1 */
#define GITEMS (NB*NP*NSLOT)   /* 1114112 */

// feat scratch: [b][pt][c], c-contiguous, padded to 136
__device__ float g_feat[(size_t)NB*NP*FPITCH];

// ---------------- packed f32x2 helpers ----------------
__device__ __forceinline__ ull pack2(float lo, float hi){
  ull r;
  asm("mov.b64 %0, {%1, %2};" : "=l"(r) : "r"(__float_as_uint(lo)), "r"(__float_as_uint(hi)));
  return r;
}
__device__ __forceinline__ void unpack2(ull v, float& lo, float& hi){
  unsigned a, b;
  asm("mov.b64 {%0, %1}, %2;" : "=r"(a), "=r"(b) : "l"(v));
  lo = __uint_as_float(a); hi = __uint_as_float(b);
}
__device__ __forceinline__ ull fma2(ull a, ull b, ull c){
  ull d;
  asm("fma.rn.f32x2 %0, %1, %2, %3;" : "=l"(d) : "l"(a), "l"(b), "l"(c));
  return d;
}

// ---------------- bilinear sample (feeds MLP; tolerance-level only) -------
__device__ __forceinline__ float bil(const float* __restrict__ base, int W, int H,
                                     float px, float py){
  float gx = 2.f*px - 1.f, gy = 2.f*py - 1.f;
  float x = ((gx + 1.f)*(float)W - 1.f)*0.5f;
  float y = ((gy + 1.f)*(float)H - 1.f)*0.5f;
  float x0f = floorf(x), y0f = floorf(y);
  float wx = x - x0f, wy = y - y0f;
  int x0 = (int)x0f, y0 = (int)y0f, x1 = x0 + 1, y1 = y0 + 1;
  bool vx0 = (x0 >= 0) && (x0 < W), vx1 = (x1 >= 0) && (x1 < W);
  bool vy0 = (y0 >= 0) && (y0 < H), vy1 = (y1 >= 0) && (y1 < H);
  float v00 = (vx0 && vy0) ? base[y0*W + x0] : 0.f;
  float v01 = (vx1 && vy0) ? base[y0*W + x1] : 0.f;
  float v10 = (vx0 && vy1) ? base[y1*W + x0] : 0.f;
  float v11 = (vx1 && vy1) ? base[y1*W + x1] : 0.f;
  return v00*(1.f-wx)*(1.f-wy) + v01*wx*(1.f-wy) + v10*(1.f-wx)*wy + v11*wx*wy;
}

// =========================================================================
// Kernel 1: per-batch top-k point selection (warp-aggregated histogram,
// shuffle-scan radix select, hybrid shfl/smem bitonic sort)
// =========================================================================
#define SM2_BYTES 99392

__global__ __launch_bounds__(1024) void k2_points(
    const float* __restrict__ coarse, const float* __restrict__ over_gen,
    const float* __restrict__ coverage, float* __restrict__ out)
{
  extern __shared__ char sm[];
  float* m1s = (float*)sm;                       // 4096 f
  float* m2s = m1s + 4096;                       // 4096 f
  ull*   keys = (ull*)(sm + 32768);              // 7168 u64 (reused as sort bufs)
  ull*   sel  = (ull*)(sm + 90112);              // 1024 u64
  unsigned* cum  = (unsigned*)(sm + 98304);      // 256
  unsigned* misc = cum + 256;                    // [0]=krem [1]=digit [2]=below [3]=cnt
  unsigned* wsum = misc + 4;                     // 8
  ull* s_pfx = (ull*)(wsum + 8);

  const int b = blockIdx.x, tid = threadIdx.x;
  const int lane = tid & 31;
  const float NEG_INF = __int_as_float(0xff800000);

  // per-pixel top-2 of 7 coarse channels
  const float* cb = coarse + (size_t)b*7*4096;
  for (int l = tid; l < 4096; l += 1024){
    float m1 = NEG_INF, m2 = NEG_INF;
    #pragma unroll
    for (int c = 0; c < 7; c++){
      float v = cb[c*4096 + l];
      if (v > m1){ m2 = m1; m1 = v; } else if (v > m2) m2 = v;
    }
    m1s[l] = m1; m2s[l] = m2;
  }
  if (tid == 0){ *s_pfx = 0ull; misc[0] = NIMP; misc[3] = 0; }
  __syncthreads();

  // uncertainty for 7168 points, bitwise-matching reference rounding
  const float* og = over_gen + (size_t)b*NOVER*2;
  for (int t = 0; t < 7; t++){
    int i = tid + t*1024;
    float px = og[i*2], py = og[i*2 + 1];
    float gx = __fsub_rn(__fmul_rn(2.f, px), 1.f);
    float gy = __fsub_rn(__fmul_rn(2.f, py), 1.f);
    float x  = __fmul_rn(__fsub_rn(__fmul_rn(__fadd_rn(gx, 1.f), 64.f), 1.f), 0.5f);
    float y  = __fmul_rn(__fsub_rn(__fmul_rn(__fadd_rn(gy, 1.f), 64.f), 1.f), 0.5f);
    float x0f = floorf(x), y0f = floorf(y);
    float wx = __fsub_rn(x, x0f), wy = __fsub_rn(y, y0f);
    float omx = __fsub_rn(1.f, wx), omy = __fsub_rn(1.f, wy);
    float x1f = __fadd_rn(x0f, 1.f), y1f = __fadd_rn(y0f, 1.f);
    bool vx0 = (x0f >= 0.f) && (x0f <= 63.f);
    bool vx1 = (x1f >= 0.f) && (x1f <= 63.f);
    bool vy0 = (y0f >= 0.f) && (y0f <= 63.f);
    bool vy1 = (y1f >= 0.f) && (y1f <= 63.f);
    int ix0 = min(max((int)x0f, 0), 63), iy0 = min(max((int)y0f, 0), 63);
    int ix1 = min(max((int)x1f, 0), 63), iy1 = min(max((int)y1f, 0), 63);
    int o00 = iy0*64 + ix0, o01 = iy0*64 + ix1, o10 = iy1*64 + ix0, o11 = iy1*64 + ix1;
    float a00 = (vx0 && vy0) ? m1s[o00] : 0.f;
    float a01 = (vx1 && vy0) ? m1s[o01] : 0.f;
    float a10 = (vx0 && vy1) ? m1s[o10] : 0.f;
    float a11 = (vx1 && vy1) ? m1s[o11] : 0.f;
    float b00 = (vx0 && vy0) ? m2s[o00] : 0.f;
    float b01 = (vx1 && vy0) ? m2s[o01] : 0.f;
    float b10 = (vx0 && vy1) ? m2s[o10] : 0.f;
    float b11 = (vx1 && vy1) ? m2s[o11] : 0.f;
    float s0 = __fadd_rn(__fadd_rn(__fadd_rn(
                 __fmul_rn(__fmul_rn(a00, omx), omy),
                 __fmul_rn(__fmul_rn(a01, wx ), omy)),
                 __fmul_rn(__fmul_rn(a10, omx), wy )),
                 __fmul_rn(__fmul_rn(a11, wx ), wy ));
    float s1 = __fadd_rn(__fadd_rn(__fadd_rn(
                 __fmul_rn(__fmul_rn(b00, omx), omy),
                 __fmul_rn(__fmul_rn(b01, wx ), omy)),
                 __fmul_rn(__fmul_rn(b10, omx), wy )),
                 __fmul_rn(__fmul_rn(b11, wx ), wy ));
    float unc = __fsub_rn(s1, s0);
    unsigned u = __float_as_uint(unc);
    unsigned mo = (u & 0x80000000u) ? ~u : (u | 0x80000000u);
    unsigned kv = ~mo;                         // ascending kv == descending unc
    keys[i] = ((ull)kv << 13) | (unsigned)i;   // tie-break: ascending index
  }
  __syncthreads();

  // radix select: 768th-smallest 45-bit key.
  // Histogram uses warp-aggregated atomics (match_any) because the float-
  // derived digits are heavily concentrated in early rounds.
  for (int r = 0; r < 6; r++){
    if (tid < 256) cum[tid] = 0;
    __syncthreads();
    ull pfx = *s_pfx; unsigned krem = misc[0];
    int shift = 40 - 8*r;
    #pragma unroll
    for (int t = 0; t < 7; t++){
      ull key = keys[tid + t*1024];
      bool act = ((key >> (shift + 8)) == pfx);
      unsigned amask = __ballot_sync(0xffffffffu, act);
      if (act){
        unsigned d = (unsigned)(key >> shift) & 255u;
        unsigned peers = __match_any_sync(amask, d);
        unsigned leader = __ffs(peers) - 1u;
        if (lane == leader) atomicAdd(&cum[d], (unsigned)__popc(peers));
      }
    }
    __syncthreads();
    unsigned cnt = 0, x = 0;
    if (tid < 256){
      cnt = cum[tid];
      x = cnt;
      #pragma unroll
      for (int o = 1; o < 32; o <<= 1){
        unsigned y = __shfl_up_sync(0xffffffffu, x, o);
        if (lane >= o) x += y;
      }
      if (lane == 31) wsum[tid >> 5] = x;
    }
    __syncthreads();
    if (tid < 256){
      unsigned add = 0;
      int w = tid >> 5;
      #pragma unroll
      for (int i2 = 0; i2 < 8; i2++) if (i2 < w) add += wsum[i2];
      unsigned le = x + add, lt = le - cnt;
      if (lt < krem && le >= krem){ misc[1] = tid; misc[2] = lt; }
    }
    __syncthreads();
    if (tid == 0){ *s_pfx = (*s_pfx << 8) | (ull)misc[1]; misc[0] -= misc[2]; }
    __syncthreads();
  }
  ull T = *s_pfx;            // exact 768th-smallest key

  // compact the 768 selected keys (warp-aggregated position allocation)
  for (int t = 0; t < 7; t++){
    ull key = keys[tid + t*1024];
    bool takeit = (key <= T);
    unsigned amask = __ballot_sync(0xffffffffu, takeit);
    if (takeit){
      unsigned rank = __popc(amask & ((1u << lane) - 1u));
      unsigned base;
      if (rank == 0) base = atomicAdd(&misc[3], (unsigned)__popc(amask));
      base = __shfl_sync(amask, base, __ffs(amask) - 1);
      unsigned pos = base + rank;
      if (pos < 1024) sel[pos] = key;
    }
  }
  __syncthreads();

  // hybrid bitonic sort of 1024 (value in register; shfl for j<32,
  // double-buffered smem exchange for j>=32 -> 1 barrier per cross stage)
  ull v = (tid < NIMP) ? sel[tid] : ~0ull;
  ull* bufA = keys;          // reuse keys region
  ull* bufB = keys + 1024;
  int  cur = 0;
  for (int k = 2; k <= 1024; k <<= 1){
    for (int j = k >> 1; j > 0; j >>= 1){
      ull other;
      if (j < 32){
        other = __shfl_xor_sync(0xffffffffu, v, j);
      } else {
        ull* buf = cur ? bufB : bufA;
        buf[tid] = v;
        __syncthreads();
        other = buf[tid ^ j];
        cur ^= 1;
      }
      bool up = ((tid & k) == 0);
      bool keepmin = (((tid & j) == 0) == up);
      bool gt = (v > other);
      v = (keepmin == gt) ? other : v;
    }
  }

  // points = concat(importance, coverage)  -> points region of d_out
  float px, py;
  if (tid < NIMP){
    int idx = (int)(v & 0x1FFFu);
    px = og[idx*2]; py = og[idx*2 + 1];
  } else {
    int j = tid - NIMP;
    px = coverage[((size_t)b*NCOV + j)*2];
    py = coverage[((size_t)b*NCOV + j)*2 + 1];
  }
  float* op = out + REND_ELEMS + ((size_t)b*NP + tid)*2;
  op[0] = px; op[1] = py;
}

// =========================================================================
// Kernel 2 (gather): one thread per (b, pt, channel-pair). 8 independent
// scattered loads in flight per thread; float2 store into g_feat.
// =========================================================================
__global__ __launch_bounds__(256) void k_gather(
    const float* __restrict__ coarse, const float* __restrict__ fine,
    const float* __restrict__ out)
{
  int i = blockIdx.x*256 + threadIdx.x;
  if (i >= GITEMS) return;
  int b  = i / (NP*NSLOT);
  int r  = i - b*(NP*NSLOT);
  int pt = r / NSLOT;
  int s  = r - pt*NSLOT;
  int c0 = 2*s;

  const float2 p = *(const float2*)(out + REND_ELEMS + ((size_t)b*NP + pt)*2);

  const float* cbase = coarse + (size_t)b*7*4096;
  const float* fbase = fine + (size_t)b*128*65536;

  float v0 = (c0 < 7) ? bil(cbase + (size_t)c0*4096, 64, 64, p.x, p.y)
                      : bil(fbase + (size_t)(c0 - 7)*65536, 256, 256, p.x, p.y);
  float* dst = g_feat + ((size_t)b*NP + pt)*FPITCH + c0;
  if (c0 + 1 < NCH){
    int c1 = c0 + 1;
    float v1 = (c1 < 7) ? bil(cbase + (size_t)c1*4096, 64, 64, p.x, p.y)
                        : bil(fbase + (size_t)(c1 - 7)*65536, 256, 256, p.x, p.y);
    *(float2*)dst = make_float2(v0, v1);
  } else {
    *dst = v0;
  }
}

// =========================================================================
// Kernel 3 (MLP): feat from g_feat (streaming), 135->256 relu ->7.
// 128 blocks (b, chunk of 128 points), 512 threads, f32x2 register tiles.
// =========================================================================
__global__ __launch_bounds__(512) void k3_head(
    const float* __restrict__ w1, const float* __restrict__ b1,
    const float* __restrict__ w2, const float* __restrict__ b2,
    float* __restrict__ out)
{
  extern __shared__ float sf[];
  float* fs  = sf;                    // 128*136
  float* wsh = fs + 128*136;          // 16*256
  float* w2s = wsh + 4096;            // 256*7
  float* hs  = w2s + 1792;            // 128*258

  const int b = blockIdx.y, chunk = blockIdx.x;
  const int tid = threadIdx.x;
  const int pbase = chunk*128;

  const float* gsrc = g_feat + ((size_t)b*NP + pbase)*FPITCH;
  for (int i = tid; i < 128*FPITCH; i += 512) fs[i] = gsrc[i];
  for (int i = tid; i < 1792; i += 512) w2s[i] = w2[i];

  const int colg = tid & 31, ptg = tid >> 5;
  const int p0 = ptg*8;
  ull acc[8][4];
  {
    ull binit[4];
    #pragma unroll
    for (int q = 0; q < 4; q++){
      int c0 = 2*colg + 64*q;
      binit[q] = pack2(b1[c0], b1[c0 + 1]);
    }
    #pragma unroll
    for (int p = 0; p < 8; p++)
      #pragma unroll
      for (int q = 0; q < 4; q++) acc[p][q] = binit[q];
  }
  for (int k0 = 0; k0 < 135; k0 += 16){
    int kc = min(16, 135 - k0);
    __syncthreads();
    for (int i = tid; i < kc*256; i += 512) wsh[i] = w1[k0*256 + i];
    __syncthreads();
    for (int r = 0; r < kc; r++){
      const ull* wrow = (const ull*)(wsh + r*256);
      ull wv0 = wrow[colg], wv1 = wrow[colg + 32], wv2 = wrow[colg + 64], wv3 = wrow[colg + 96];
      const float* fcol = fs + (k0 + r);
      #pragma unroll
      for (int p = 0; p < 8; p++){
        float fv = fcol[(p0 + p)*FPITCH];
        ull ff = pack2(fv, fv);
        acc[p][0] = fma2(ff, wv0, acc[p][0]);
        acc[p][1] = fma2(ff, wv1, acc[p][1]);
        acc[p][2] = fma2(ff, wv2, acc[p][2]);
        acc[p][3] = fma2(ff, wv3, acc[p][3]);
      }
    }
  }

  #pragma unroll
  for (int p = 0; p < 8; p++){
    #pragma unroll
    for (int q = 0; q < 4; q++){
      float lo, hi; unpack2(acc[p][q], lo, hi);
      int c0 = 2*colg + 64*q;
      hs[(p0 + p)*258 + c0]     = fmaxf(lo, 0.f);
      hs[(p0 + p)*258 + c0 + 1] = fmaxf(hi, 0.f);
    }
  }
  __syncthreads();

  for (int t = tid; t < 896; t += 512){
    int pt = t / 7, cls = t - pt*7;
    const float* hrow = hs + pt*258;
    float s = b2[cls];
    #pragma unroll 8
    for (int k = 0; k < 256; k++) s = fmaf(hrow[k], w2s[k*7 + cls], s);
    out[((size_t)b*7 + cls)*NP + pbase + pt] = s;
  }
}

// =========================================================================
extern "C" void kernel_launch(void* const* d_in, const int* in_sizes, int n_in,
                              void* d_out, int out_size){
  const float *fine = nullptr, *coarse = nullptr, *w1 = nullptr, *b1 = nullptr,
              *w2 = nullptr, *b2 = nullptr, *og = nullptr, *cov = nullptr;
  for (int i = 0; i < n_in; i++){
    switch (in_sizes[i]){
      case 134217728: fine   = (const float*)d_in[i]; break;
      case 458752:    coarse = (const float*)d_in[i]; break;
      case 34560:     w1     = (const float*)d_in[i]; break;
      case 256:       b1     = (const float*)d_in[i]; break;
      case 1792:      w2     = (const float*)d_in[i]; break;
      case 7:         b2     = (const float*)d_in[i]; break;
      case 229376:    og     = (const float*)d_in[i]; break;
      case 8192:      cov    = (const float*)d_in[i]; break;
      default: break;
    }
  }
  float* out = (float*)d_out;

  const size_t sm3 = (size_t)(128*FPITCH + 4096 + 1792 + 128*258)*sizeof(float); // ~225KB
  cudaFuncSetAttribute(k2_points, cudaFuncAttributeMaxDynamicSharedMemorySize, SM2_BYTES);
  cudaFuncSetAttribute(k3_head, cudaFuncAttributeMaxDynamicSharedMemorySize, (int)sm3);

  k2_points<<<NB, 1024, SM2_BYTES>>>(coarse, og, cov, out);
  k_gather<<<(GITEMS + 255)/256, 256>>>(coarse, fine, out);
  k3_head<<<dim3(8, NB), 512, sm3>>>(w1, b1, w2, b2, out);
}

// round 10
// speedup vs baseline: 1.1483x; 1.1483x over previous
#include <cuda_runtime.h>
#include <cstdint>

typedef unsigned long long ull;

#define NB 16
#define NOVER 7168
#define NP 1024
#define NIMP 768
#define NCOV 256
#define REND_ELEMS (NB*7*NP)   /* 114688 */
#define NCH 135
#define FPITCH 136
#define GITEMS (NB*NP*NCH)     /* 2211840 */
#define HPTS 64                /* points per head block */

// feat scratch: [b][pt][c], c-contiguous, padded to 136
__device__ float g_feat[(size_t)NB*NP*FPITCH];

// ---------------- packed f32x2 helpers ----------------
__device__ __forceinline__ ull pack2(float lo, float hi){
  ull r;
  asm("mov.b64 %0, {%1, %2};" : "=l"(r) : "r"(__float_as_uint(lo)), "r"(__float_as_uint(hi)));
  return r;
}
__device__ __forceinline__ void unpack2(ull v, float& lo, float& hi){
  unsigned a, b;
  asm("mov.b64 {%0, %1}, %2;" : "=r"(a), "=r"(b) : "l"(v));
  lo = __uint_as_float(a); hi = __uint_as_float(b);
}
__device__ __forceinline__ ull fma2(ull a, ull b, ull c){
  ull d;
  asm("fma.rn.f32x2 %0, %1, %2, %3;" : "=l"(d) : "l"(a), "l"(b), "l"(c));
  return d;
}

// ---------------- bilinear sample (feeds MLP; tolerance-level only) -------
__device__ __forceinline__ float bil(const float* __restrict__ base, int W, int H,
                                     float px, float py){
  float gx = 2.f*px - 1.f, gy = 2.f*py - 1.f;
  float x = ((gx + 1.f)*(float)W - 1.f)*0.5f;
  float y = ((gy + 1.f)*(float)H - 1.f)*0.5f;
  float x0f = floorf(x), y0f = floorf(y);
  float wx = x - x0f, wy = y - y0f;
  int x0 = (int)x0f, y0 = (int)y0f, x1 = x0 + 1, y1 = y0 + 1;
  bool vx0 = (x0 >= 0) && (x0 < W), vx1 = (x1 >= 0) && (x1 < W);
  bool vy0 = (y0 >= 0) && (y0 < H), vy1 = (y1 >= 0) && (y1 < H);
  float v00 = (vx0 && vy0) ? base[y0*W + x0] : 0.f;
  float v01 = (vx1 && vy0) ? base[y0*W + x1] : 0.f;
  float v10 = (vx0 && vy1) ? base[y1*W + x0] : 0.f;
  float v11 = (vx1 && vy1) ? base[y1*W + x1] : 0.f;
  return v00*(1.f-wx)*(1.f-wy) + v01*wx*(1.f-wy) + v10*(1.f-wx)*wy + v11*wx*wy;
}

// =========================================================================
// Kernel 1: per-batch top-k (round-8 version: plain smem-atomic histogram,
// shuffle-scan radix select, hybrid shfl/smem bitonic sort)
// =========================================================================
#define SM2_BYTES 99392

__global__ __launch_bounds__(1024) void k2_points(
    const float* __restrict__ coarse, const float* __restrict__ over_gen,
    const float* __restrict__ coverage, float* __restrict__ out)
{
  extern __shared__ char sm[];
  float* m1s = (float*)sm;                       // 4096 f
  float* m2s = m1s + 4096;                       // 4096 f
  ull*   keys = (ull*)(sm + 32768);              // 7168 u64 (reused as sort bufs)
  ull*   sel  = (ull*)(sm + 90112);              // 1024 u64
  unsigned* cum  = (unsigned*)(sm + 98304);      // 256
  unsigned* misc = cum + 256;                    // [0]=krem [1]=digit [2]=below [3]=cnt
  unsigned* wsum = misc + 4;                     // 8
  ull* s_pfx = (ull*)(wsum + 8);

  const int b = blockIdx.x, tid = threadIdx.x;
  const int lane = tid & 31;
  const float NEG_INF = __int_as_float(0xff800000);

  const float* cb = coarse + (size_t)b*7*4096;
  for (int l = tid; l < 4096; l += 1024){
    float m1 = NEG_INF, m2 = NEG_INF;
    #pragma unroll
    for (int c = 0; c < 7; c++){
      float v = cb[c*4096 + l];
      if (v > m1){ m2 = m1; m1 = v; } else if (v > m2) m2 = v;
    }
    m1s[l] = m1; m2s[l] = m2;
  }
  if (tid == 0){ *s_pfx = 0ull; misc[0] = NIMP; misc[3] = 0; }
  __syncthreads();

  const float* og = over_gen + (size_t)b*NOVER*2;
  for (int t = 0; t < 7; t++){
    int i = tid + t*1024;
    float px = og[i*2], py = og[i*2 + 1];
    float gx = __fsub_rn(__fmul_rn(2.f, px), 1.f);
    float gy = __fsub_rn(__fmul_rn(2.f, py), 1.f);
    float x  = __fmul_rn(__fsub_rn(__fmul_rn(__fadd_rn(gx, 1.f), 64.f), 1.f), 0.5f);
    float y  = __fmul_rn(__fsub_rn(__fmul_rn(__fadd_rn(gy, 1.f), 64.f), 1.f), 0.5f);
    float x0f = floorf(x), y0f = floorf(y);
    float wx = __fsub_rn(x, x0f), wy = __fsub_rn(y, y0f);
    float omx = __fsub_rn(1.f, wx), omy = __fsub_rn(1.f, wy);
    float x1f = __fadd_rn(x0f, 1.f), y1f = __fadd_rn(y0f, 1.f);
    bool vx0 = (x0f >= 0.f) && (x0f <= 63.f);
    bool vx1 = (x1f >= 0.f) && (x1f <= 63.f);
    bool vy0 = (y0f >= 0.f) && (y0f <= 63.f);
    bool vy1 = (y1f >= 0.f) && (y1f <= 63.f);
    int ix0 = min(max((int)x0f, 0), 63), iy0 = min(max((int)y0f, 0), 63);
    int ix1 = min(max((int)x1f, 0), 63), iy1 = min(max((int)y1f, 0), 63);
    int o00 = iy0*64 + ix0, o01 = iy0*64 + ix1, o10 = iy1*64 + ix0, o11 = iy1*64 + ix1;
    float a00 = (vx0 && vy0) ? m1s[o00] : 0.f;
    float a01 = (vx1 && vy0) ? m1s[o01] : 0.f;
    float a10 = (vx0 && vy1) ? m1s[o10] : 0.f;
    float a11 = (vx1 && vy1) ? m1s[o11] : 0.f;
    float b00 = (vx0 && vy0) ? m2s[o00] : 0.f;
    float b01 = (vx1 && vy0) ? m2s[o01] : 0.f;
    float b10 = (vx0 && vy1) ? m2s[o10] : 0.f;
    float b11 = (vx1 && vy1) ? m2s[o11] : 0.f;
    float s0 = __fadd_rn(__fadd_rn(__fadd_rn(
                 __fmul_rn(__fmul_rn(a00, omx), omy),
                 __fmul_rn(__fmul_rn(a01, wx ), omy)),
                 __fmul_rn(__fmul_rn(a10, omx), wy )),
                 __fmul_rn(__fmul_rn(a11, wx ), wy ));
    float s1 = __fadd_rn(__fadd_rn(__fadd_rn(
                 __fmul_rn(__fmul_rn(b00, omx), omy),
                 __fmul_rn(__fmul_rn(b01, wx ), omy)),
                 __fmul_rn(__fmul_rn(b10, omx), wy )),
                 __fmul_rn(__fmul_rn(b11, wx ), wy ));
    float unc = __fsub_rn(s1, s0);
    unsigned u = __float_as_uint(unc);
    unsigned mo = (u & 0x80000000u) ? ~u : (u | 0x80000000u);
    unsigned kv = ~mo;                         // ascending kv == descending unc
    keys[i] = ((ull)kv << 13) | (unsigned)i;   // tie-break: ascending index
  }
  __syncthreads();

  // radix select: 768th-smallest 45-bit key (5 barriers/round)
  for (int r = 0; r < 6; r++){
    if (tid < 256) cum[tid] = 0;
    __syncthreads();
    ull pfx = *s_pfx; unsigned krem = misc[0];
    int shift = 40 - 8*r;
    #pragma unroll
    for (int t = 0; t < 7; t++){
      ull key = keys[tid + t*1024];
      if ((key >> (shift + 8)) == pfx)
        atomicAdd(&cum[(unsigned)(key >> shift) & 255u], 1u);
    }
    __syncthreads();
    unsigned cnt = 0, x = 0;
    if (tid < 256){
      cnt = cum[tid];
      x = cnt;
      #pragma unroll
      for (int o = 1; o < 32; o <<= 1){
        unsigned y = __shfl_up_sync(0xffffffffu, x, o);
        if (lane >= o) x += y;
      }
      if (lane == 31) wsum[tid >> 5] = x;
    }
    __syncthreads();
    if (tid < 256){
      unsigned add = 0;
      int w = tid >> 5;
      #pragma unroll
      for (int i2 = 0; i2 < 8; i2++) if (i2 < w) add += wsum[i2];
      unsigned le = x + add, lt = le - cnt;
      if (lt < krem && le >= krem){ misc[1] = tid; misc[2] = lt; }
    }
    __syncthreads();
    if (tid == 0){ *s_pfx = (*s_pfx << 8) | (ull)misc[1]; misc[0] -= misc[2]; }
    __syncthreads();
  }
  ull T = *s_pfx;            // exact 768th-smallest key

  // compact the 768 selected keys (unordered)
  for (int t = 0; t < 7; t++){
    ull key = keys[tid + t*1024];
    if (key <= T){
      unsigned pos = atomicAdd(&misc[3], 1u);
      if (pos < 1024) sel[pos] = key;
    }
  }
  __syncthreads();

  // hybrid bitonic sort of 1024
  ull v = (tid < NIMP) ? sel[tid] : ~0ull;
  ull* bufA = keys;
  ull* bufB = keys + 1024;
  int  cur = 0;
  for (int k = 2; k <= 1024; k <<= 1){
    for (int j = k >> 1; j > 0; j >>= 1){
      ull other;
      if (j < 32){
        other = __shfl_xor_sync(0xffffffffu, v, j);
      } else {
        ull* buf = cur ? bufB : bufA;
        buf[tid] = v;
        __syncthreads();
        other = buf[tid ^ j];
        cur ^= 1;
      }
      bool up = ((tid & k) == 0);
      bool keepmin = (((tid & j) == 0) == up);
      bool gt = (v > other);
      v = (keepmin == gt) ? other : v;
    }
  }

  float px, py;
  if (tid < NIMP){
    int idx = (int)(v & 0x1FFFu);
    px = og[idx*2]; py = og[idx*2 + 1];
  } else {
    int j = tid - NIMP;
    px = coverage[((size_t)b*NCOV + j)*2];
    py = coverage[((size_t)b*NCOV + j)*2 + 1];
  }
  float* op = out + REND_ELEMS + ((size_t)b*NP + tid)*2;
  op[0] = px; op[1] = py;
}

// =========================================================================
// Kernel 2 (gather, round-8 version): one thread per (b, pt, c).
// =========================================================================
__global__ __launch_bounds__(256) void k_gather(
    const float* __restrict__ coarse, const float* __restrict__ fine,
    const float* __restrict__ out)
{
  int i = blockIdx.x*256 + threadIdx.x;
  if (i >= GITEMS) return;
  int b  = i / (NP*NCH);
  int r  = i - b*(NP*NCH);
  int pt = r / NCH;
  int c  = r - pt*NCH;

  const float2 p = *(const float2*)(out + REND_ELEMS + ((size_t)b*NP + pt)*2);

  float val;
  if (c < 7) val = bil(coarse + ((size_t)b*7 + c)*4096, 64, 64, p.x, p.y);
  else       val = bil(fine + ((size_t)b*128 + (c - 7))*65536, 256, 256, p.x, p.y);
  g_feat[((size_t)b*NP + pt)*FPITCH + c] = val;
}

// =========================================================================
// Kernel 3 (MLP): 64 pts/block, 256 threads, grid 256 -> all SMs busy.
// GEMM1 in f32x2 register tiles; GEMM2 straight from the accumulators via
// intra-warp shfl butterfly (the 32 colg threads of a point group are one
// warp). No hs staging buffer -> smem 225KB -> 58KB.
// =========================================================================
__global__ __launch_bounds__(256) void k3_head(
    const float* __restrict__ w1, const float* __restrict__ b1,
    const float* __restrict__ w2, const float* __restrict__ b2,
    float* __restrict__ out)
{
  extern __shared__ float sf[];
  float* fs  = sf;                    // 64*136   = 8704 f
  float* wsh = fs + HPTS*FPITCH;      // 16*256   = 4096 f
  float* w2s = wsh + 4096;            // 256*7    = 1792 f

  const int b = blockIdx.y, chunk = blockIdx.x;   // chunk 0..15
  const int tid = threadIdx.x;                    // 256 threads, 8 warps
  const int pbase = chunk*HPTS;

  const float* gsrc = g_feat + ((size_t)b*NP + pbase)*FPITCH;
  for (int i = tid; i < HPTS*FPITCH; i += 256) fs[i] = gsrc[i];
  for (int i = tid; i < 1792; i += 256) w2s[i] = w2[i];

  const int colg = tid & 31, ptg = tid >> 5;      // ptg 0..7 -> 8 pts each
  const int p0 = ptg*8;
  ull acc[8][4];
  {
    ull binit[4];
    #pragma unroll
    for (int q = 0; q < 4; q++){
      int c0 = 2*colg + 64*q;
      binit[q] = pack2(b1[c0], b1[c0 + 1]);
    }
    #pragma unroll
    for (int p = 0; p < 8; p++)
      #pragma unroll
      for (int q = 0; q < 4; q++) acc[p][q] = binit[q];
  }
  for (int k0 = 0; k0 < 135; k0 += 16){
    int kc = min(16, 135 - k0);
    __syncthreads();
    for (int i = tid; i < kc*256; i += 256) wsh[i] = w1[k0*256 + i];
    __syncthreads();
    for (int r = 0; r < kc; r++){
      const ull* wrow = (const ull*)(wsh + r*256);
      ull wv0 = wrow[colg], wv1 = wrow[colg + 32], wv2 = wrow[colg + 64], wv3 = wrow[colg + 96];
      const float* fcol = fs + (k0 + r);
      #pragma unroll
      for (int p = 0; p < 8; p++){
        float fv = fcol[(p0 + p)*FPITCH];
        ull ff = pack2(fv, fv);
        acc[p][0] = fma2(ff, wv0, acc[p][0]);
        acc[p][1] = fma2(ff, wv1, acc[p][1]);
        acc[p][2] = fma2(ff, wv2, acc[p][2]);
        acc[p][3] = fma2(ff, wv3, acc[p][3]);
      }
    }
  }

  // GEMM2 from registers: relu -> per-point partial rend over this lane's
  // 8 h-columns -> warp butterfly reduction -> write.
  #pragma unroll
  for (int p = 0; p < 8; p++){
    float pr[7];
    #pragma unroll
    for (int cls = 0; cls < 7; cls++) pr[cls] = 0.f;
    #pragma unroll
    for (int q = 0; q < 4; q++){
      float lo, hi; unpack2(acc[p][q], lo, hi);
      lo = fmaxf(lo, 0.f); hi = fmaxf(hi, 0.f);
      int c0 = 2*colg + 64*q;
      const float* wl = w2s + c0*7;
      #pragma unroll
      for (int cls = 0; cls < 7; cls++)
        pr[cls] = fmaf(lo, wl[cls], fmaf(hi, wl[7 + cls], pr[cls]));
    }
    #pragma unroll
    for (int cls = 0; cls < 7; cls++){
      #pragma unroll
      for (int o = 16; o >= 1; o >>= 1)
        pr[cls] += __shfl_xor_sync(0xffffffffu, pr[cls], o);
    }
    if (colg < 7){
      int cls = colg;
      out[((size_t)b*7 + cls)*NP + pbase + p0 + p] = pr[cls] + b2[cls];
    }
  }
}

// =========================================================================
extern "C" void kernel_launch(void* const* d_in, const int* in_sizes, int n_in,
                              void* d_out, int out_size){
  const float *fine = nullptr, *coarse = nullptr, *w1 = nullptr, *b1 = nullptr,
              *w2 = nullptr, *b2 = nullptr, *og = nullptr, *cov = nullptr;
  for (int i = 0; i < n_in; i++){
    switch (in_sizes[i]){
      case 134217728: fine   = (const float*)d_in[i]; break;
      case 458752:    coarse = (const float*)d_in[i]; break;
      case 34560:     w1     = (const float*)d_in[i]; break;
      case 256:       b1     = (const float*)d_in[i]; break;
      case 1792:      w2     = (const float*)d_in[i]; break;
      case 7:         b2     = (const float*)d_in[i]; break;
      case 229376:    og     = (const float*)d_in[i]; break;
      case 8192:      cov    = (const float*)d_in[i]; break;
      default: break;
    }
  }
  float* out = (float*)d_out;

  const size_t sm3 = (size_t)(HPTS*FPITCH + 4096 + 1792)*sizeof(float); // 58368
  cudaFuncSetAttribute(k2_points, cudaFuncAttributeMaxDynamicSharedMemorySize, SM2_BYTES);
  cudaFuncSetAttribute(k3_head, cudaFuncAttributeMaxDynamicSharedMemorySize, (int)sm3);

  k2_points<<<NB, 1024, SM2_BYTES>>>(coarse, og, cov, out);
  k_gather<<<(GITEMS + 255)/256, 256>>>(coarse, fine, out);
  k3_head<<<dim3(16, NB), 256, sm3>>>(w1, b1, w2, b2, out);
}